// round 9
// baseline (speedup 1.0000x reference)
#include <cuda_runtime.h>
#include <cuda_bf16.h>

// Shapes (fixed): B=32, D=64, N=254, L=16, H=128, P=96
#define NB 32
#define ND 64
#define NN 254
#define NL 16
#define NH 128
#define NP 96
#define PAIRS (NB*ND)          // 2048
#define XPP (NN*NL)            // 4064 floats per (b,d) pair
#define OUT_T_ELEMS (NB*NP*ND) // 196608
#define NPRE 38                // producer blocks
#define NBLK 512               // persistent blocks
#define PPB  (PAIRS/NBLK)      // 4 pairs per block

// ---- shared precomputed tensors (tiny) ----
__device__ __align__(16) float g_constvec[NH];
__device__ __align__(16) float g_M[NN*NL];   // M[n,l] = pos[n,:] . W_enc[l,:]
__device__ __align__(16) float g_D2[NN];     // pos[n,:] . constvec
__device__ __align__(16) float g_G[NL*NL];   // G[l',l] = W_enc[l',:] . W_enc[l,:]
__device__ __align__(16) float g_u[NL];      // W_enc[l,:] . constvec
__device__ __align__(16) float g_wb[NL];     // W_enc[l,:] . b_enc
__device__ float g_s0;                        // b_enc . constvec
__device__ int g_flag1;                       // constvec ready (monotone across replays)
__device__ int g_done;                        // precompute producers done (monotone)

__device__ __forceinline__ int ld_acq(const int* p) {
    int v;
    asm volatile("ld.acquire.gpu.global.b32 %0, [%1];" : "=r"(v) : "l"(p));
    return v;
}

// vectorized length-128 dot with 4 accumulators
__device__ __forceinline__ float dot128(const float4* __restrict__ a,
                                        const float4* __restrict__ b) {
    float s0=0.f, s1=0.f, s2=0.f, s3=0.f;
    #pragma unroll
    for (int i = 0; i < 32; i += 4) {
        float4 a0=a[i],   b0=b[i];
        float4 a1=a[i+1], b1=b[i+1];
        float4 a2=a[i+2], b2=b[i+2];
        float4 a3=a[i+3], b3=b[i+3];
        s0 += a0.x*b0.x + a0.y*b0.y + a0.z*b0.z + a0.w*b0.w;
        s1 += a1.x*b1.x + a1.y*b1.y + a1.z*b1.z + a1.w*b1.w;
        s2 += a2.x*b2.x + a2.y*b2.y + a2.z*b2.z + a2.w*b2.w;
        s3 += a3.x*b3.x + a3.y*b3.y + a3.z*b3.z + a3.w*b3.w;
    }
    return (s0+s1)+(s2+s3);
}

__global__ __launch_bounds__(128, 4)
void k_all(const float* __restrict__ x, float* __restrict__ x_copy,
           const float* __restrict__ W_enc, const float* __restrict__ b_enc,
           const float* __restrict__ pos,
           const float* __restrict__ W1, const float* __restrict__ b1,
           const float* __restrict__ W2, const float* __restrict__ b2,
           float* __restrict__ out_t) {
    __shared__ __align__(16) float redq[4][NL];   // per-warp quarter reductions
    __shared__ __align__(16) float xsumS[NL];
    __shared__ __align__(16) float vS[NL];
    __shared__ __align__(16) float pooledS[NL];   // UNNORMALIZED pooled
    __shared__ float warpsum[4];
    __shared__ __align__(16) float red7[4][NP];   // FF cross-warp partials
    __shared__ float sS, invS;

    const int tid  = threadIdx.x;
    const int pid  = blockIdx.x;
    const int lane = tid & 31;
    const int wrp  = tid >> 5;
    const int q    = tid & 3;          // l-quarter index
    const int r    = tid >> 2;         // row-within-32 index
    const float4* __restrict__ pos4 = (const float4*)pos;
    const float4* __restrict__ W4   = (const float4*)W_enc;

    // Prologue: prefetch pair 0 for this block (long-latency, overlaps precompute)
    float4 xva[8], xvb[8];
    {
        const float4* xp0 = (const float4*)(x + (size_t)pid * XPP);
        #pragma unroll
        for (int j = 0; j < 8; j++) {
            int i = tid + j*128;
            xva[j] = (i < XPP/4) ? __ldcs(xp0 + i) : make_float4(0.f,0.f,0.f,0.f);
        }
    }

    // ---------- inline precompute (first NPRE blocks; all blocks co-resident) ----------
    if (pid < NPRE) {
        if (pid == 0) {
            float a0=0.f, a1=0.f, a2=0.f, a3=0.f;
            #pragma unroll 2
            for (int n = 0; n < 252; n += 4) {
                a0 += __ldg(pos + (n+0)*NH + tid);
                a1 += __ldg(pos + (n+1)*NH + tid);
                a2 += __ldg(pos + (n+2)*NH + tid);
                a3 += __ldg(pos + (n+3)*NH + tid);
            }
            a0 += __ldg(pos + 252*NH + tid);
            a1 += __ldg(pos + 253*NH + tid);
            g_constvec[tid] = (float)NN * b_enc[tid] + ((a0+a1)+(a2+a3));
            __threadfence();
            __syncthreads();
            if (tid == 0) atomicAdd(&g_flag1, 1);
        } else if (pid <= 34) {
            int j = (pid-1)*128 + tid;
            if (j < NN*NL) {                         // M
                g_M[j] = dot128(pos4 + (j>>4)*32, W4 + (j&15)*32);
            } else if (j < NN*NL + NL*NL) {          // G
                int k = j - NN*NL;
                g_G[k] = dot128(W4 + (k>>4)*32, W4 + (k&15)*32);
            }
        } else {
            if (tid == 0) { while (ld_acq(&g_flag1) == 0) {} }
            __syncthreads();
            const float4* cv4 = (const float4*)g_constvec;
            int j = (pid-35)*128 + tid;
            if (j < NN) {                            // D2
                g_D2[j] = dot128(pos4 + j*32, cv4);
            } else if (j < NN + NL) {                // u
                g_u[j-NN] = dot128(W4 + (j-NN)*32, cv4);
            } else if (j < NN + 2*NL) {              // wb
                g_wb[j-NN-NL] = dot128(W4 + (j-NN-NL)*32, (const float4*)b_enc);
            } else if (j == NN + 2*NL) {             // s0
                g_s0 = dot128((const float4*)b_enc, cv4);
            }
        }
        __threadfence();
        __syncthreads();
        if (tid == 0) atomicAdd(&g_done, 1);
    }
    // one-time wait for precompute (overlaps prologue x-load latency elsewhere)
    if (tid == 64) { while (ld_acq(&g_done) < NPRE) {} }
    // (next __syncthreads publishes to whole block)

    // ---------- persistent pipelined loop over PPB pairs ----------
    #pragma unroll 1
    for (int it = 0; it < PPB; it++) {
        const int pair = pid + it*NBLK;

        // 1) prefetch NEXT pair into xvb (not consumed this iteration)
        if (it < PPB-1) {
            const float4* xpn = (const float4*)(x + (size_t)(pair + NBLK) * XPP);
            #pragma unroll
            for (int j = 0; j < 8; j++) {
                int i = tid + j*128;
                xvb[j] = (i < XPP/4) ? __ldcs(xpn + i) : make_float4(0.f,0.f,0.f,0.f);
            }
        }

        // 2) passthrough copy of CURRENT pair + xsum partials (data already in regs)
        float4* xc4 = (float4*)(x_copy + (size_t)pair * XPP);
        float ls0=0.f, ls1=0.f, ls2=0.f, ls3=0.f;
        #pragma unroll
        for (int j = 0; j < 8; j++) {
            int i = tid + j*128;
            if (i < XPP/4) {
                __stcs(xc4 + i, xva[j]);
                ls0 += xva[j].x; ls1 += xva[j].y; ls2 += xva[j].z; ls3 += xva[j].w;
            }
        }
        #pragma unroll
        for (int m = 4; m <= 16; m <<= 1) {
            ls0 += __shfl_xor_sync(0xffffffffu, ls0, m);
            ls1 += __shfl_xor_sync(0xffffffffu, ls1, m);
            ls2 += __shfl_xor_sync(0xffffffffu, ls2, m);
            ls3 += __shfl_xor_sync(0xffffffffu, ls3, m);
        }
        if (lane < 4) {
            float* rr = &redq[wrp][lane*4];
            rr[0] = ls0; rr[1] = ls1; rr[2] = ls2; rr[3] = ls3;
        }
        __syncthreads();                                    // SYNC 1

        if (tid < NL)
            xsumS[tid] = (redq[0][tid] + redq[1][tid]) + (redq[2][tid] + redq[3][tid]);
        __syncthreads();                                    // SYNC 2

        if (tid < NL) {
            float a = g_u[tid];
            #pragma unroll
            for (int lp = 0; lp < NL; lp++) a += xsumS[lp] * g_G[lp*NL + tid];
            vS[tid] = a;
        }
        if (tid == 16) {
            float a = g_s0;
            #pragma unroll
            for (int l = 0; l < NL; l++) a += xsumS[l] * g_wb[l];
            sS = a;
        }
        __syncthreads();                                    // SYNC 3

        // 3) fused score + pool
        float4 vq  = ((const float4*)vS)[q];
        float4 xsq = ((const float4*)xsumS)[q];
        const float sloc = sS;
        float myabs = 0.f;
        float p0=0.f, p1=0.f, p2=0.f, p3=0.f;
        #pragma unroll
        for (int j = 0; j < 8; j++) {
            int n = j*32 + r;
            float part = 0.f;
            float d2 = 0.f;
            if (n < NN) {
                float4 m = *(const float4*)(g_M + n*NL + q*4);
                part = xva[j].x*vq.x + xva[j].y*vq.y + xva[j].z*vq.z + xva[j].w*vq.w
                     + xsq.x*m.x + xsq.y*m.y + xsq.z*m.z + xsq.w*m.w;
                d2 = g_D2[n];
            }
            part += __shfl_xor_sync(0xffffffffu, part, 1);
            part += __shfl_xor_sync(0xffffffffu, part, 2);
            float a = part + sloc + d2;
            if (n < NN) {
                p0 += xva[j].x * a;
                p1 += xva[j].y * a;
                p2 += xva[j].z * a;
                p3 += xva[j].w * a;
                if (q == 0) myabs += fabsf(a);
            }
        }
        #pragma unroll
        for (int m = 4; m <= 16; m <<= 1) {
            p0 += __shfl_xor_sync(0xffffffffu, p0, m);
            p1 += __shfl_xor_sync(0xffffffffu, p1, m);
            p2 += __shfl_xor_sync(0xffffffffu, p2, m);
            p3 += __shfl_xor_sync(0xffffffffu, p3, m);
            myabs += __shfl_xor_sync(0xffffffffu, myabs, m);
        }
        if (lane < 4) {
            float* rr = &redq[wrp][lane*4];
            rr[0] = p0; rr[1] = p1; rr[2] = p2; rr[3] = p3;
        }
        if (lane == 0) warpsum[wrp] = myabs;
        __syncthreads();                                    // SYNC 4

        if (tid < NL)
            pooledS[tid] = (redq[0][tid] + redq[1][tid]) + (redq[2][tid] + redq[3][tid]);
        if (tid == 16)
            invS = 1.0f / ((warpsum[0] + warpsum[1]) + (warpsum[2] + warpsum[3]));
        __syncthreads();                                    // SYNC 5

        // 4) FF: warp w owns h = 32w + lane; hidden in-register, shfl-broadcast
        float hdn;
        {
            int h = wrp*32 + lane;
            float a = 0.f;
            #pragma unroll
            for (int l = 0; l < NL; l++) a += pooledS[l] * __ldg(W1 + l*NH + h);
            a = b1[h] + a * invS;
            hdn = a > 0.f ? a : 0.2f * a;
        }
        {
            const float4* __restrict__ W24 = (const float4*)W2;  // [h][24] float4s
            float4 acc = make_float4(0.f, 0.f, 0.f, 0.f);
            #pragma unroll 8
            for (int hh = 0; hh < 32; hh++) {
                float hv = __shfl_sync(0xffffffffu, hdn, hh);
                if (lane < 24) {
                    int h = wrp*32 + hh;
                    float4 w4 = __ldg(&W24[h*24 + lane]);
                    acc.x += hv*w4.x; acc.y += hv*w4.y; acc.z += hv*w4.z; acc.w += hv*w4.w;
                }
            }
            if (lane < 24) ((float4*)red7[wrp])[lane] = acc;
        }
        __syncthreads();                                    // SYNC 6
        if (tid < NP) {
            float a = b2[tid] + (red7[0][tid] + red7[1][tid]) + (red7[2][tid] + red7[3][tid]);
            int b = pair >> 6, d = pair & 63;
            out_t[b*(NP*ND) + tid*ND + d] = a;
        }

        // 5) rotate buffers
        #pragma unroll
        for (int j = 0; j < 8; j++) xva[j] = xvb[j];
    }
}

extern "C" void kernel_launch(void* const* d_in, const int* in_sizes, int n_in,
                              void* d_out, int out_size) {
    const float* x     = (const float*)d_in[0];
    const float* W_enc = (const float*)d_in[1];
    const float* b_enc = (const float*)d_in[2];
    const float* W1    = (const float*)d_in[3];
    const float* b1    = (const float*)d_in[4];
    const float* W2    = (const float*)d_in[5];
    const float* b2    = (const float*)d_in[6];
    const float* pos   = (const float*)d_in[7];

    float* out   = (float*)d_out;          // (B,P,D) first
    float* xcopy = out + OUT_T_ELEMS;      // then p = x passthrough

    k_all<<<NBLK, 128>>>(x, xcopy, W_enc, b_enc, pos, W1, b1, W2, b2, out);
}

// round 10
// speedup vs baseline: 1.1577x; 1.1577x over previous
#include <cuda_runtime.h>
#include <cuda_bf16.h>

// Shapes (fixed): B=32, D=64, N=254, L=16, H=128, P=96
#define NB 32
#define ND 64
#define NN 254
#define NL 16
#define NH 128
#define NP 96
#define PAIRS (NB*ND)          // 2048
#define XPP (NN*NL)            // 4064 floats per (b,d) pair
#define OUT_T_ELEMS (NB*NP*ND) // 196608
#define NPRE 38                // producer blocks

// ---- shared precomputed tensors (tiny) ----
__device__ __align__(16) float g_constvec[NH];
__device__ __align__(16) float g_M[NN*NL];   // M[n,l] = pos[n,:] . W_enc[l,:]
__device__ __align__(16) float g_D2[NN];     // pos[n,:] . constvec
__device__ __align__(16) float g_G[NL*NL];   // G[l',l] = W_enc[l',:] . W_enc[l,:]
__device__ __align__(16) float g_u[NL];      // W_enc[l,:] . constvec
__device__ __align__(16) float g_wb[NL];     // W_enc[l,:] . b_enc
__device__ __align__(16) float g_s0pad[4];   // [0] = b_enc . constvec
__device__ int g_flag1;                       // constvec ready (monotone across replays)
__device__ int g_done;                        // precompute producers done (monotone)

__device__ __forceinline__ int ld_acq(const int* p) {
    int v;
    asm volatile("ld.acquire.gpu.global.b32 %0, [%1];" : "=r"(v) : "l"(p));
    return v;
}

// vectorized length-128 dot with 4 accumulators
__device__ __forceinline__ float dot128(const float4* __restrict__ a,
                                        const float4* __restrict__ b) {
    float s0=0.f, s1=0.f, s2=0.f, s3=0.f;
    #pragma unroll
    for (int i = 0; i < 32; i += 4) {
        float4 a0=a[i],   b0=b[i];
        float4 a1=a[i+1], b1=b[i+1];
        float4 a2=a[i+2], b2=b[i+2];
        float4 a3=a[i+3], b3=b[i+3];
        s0 += a0.x*b0.x + a0.y*b0.y + a0.z*b0.z + a0.w*b0.w;
        s1 += a1.x*b1.x + a1.y*b1.y + a1.z*b1.z + a1.w*b1.w;
        s2 += a2.x*b2.x + a2.y*b2.y + a2.z*b2.z + a2.w*b2.w;
        s3 += a3.x*b3.x + a3.y*b3.y + a3.z*b3.z + a3.w*b3.w;
    }
    return (s0+s1)+(s2+s3);
}

__global__ __launch_bounds__(128, 8)
void k_all(const float* __restrict__ x, float* __restrict__ x_copy,
           const float* __restrict__ W_enc, const float* __restrict__ b_enc,
           const float* __restrict__ pos,
           const float* __restrict__ W1, const float* __restrict__ b1,
           const float* __restrict__ W2, const float* __restrict__ b2,
           float* __restrict__ out_t) {
    const int tid  = threadIdx.x;
    const int pid  = blockIdx.x;
    const int lane = tid & 31;
    const int wrp  = tid >> 5;
    const int q    = lane & 3;         // l-quarter index
    const int r    = lane >> 2;        // row-within-8 index
    const float4* __restrict__ pos4 = (const float4*)pos;
    const float4* __restrict__ W4   = (const float4*)W_enc;

    // ---------- inline precompute (first NPRE blocks; wave-1 co-resident) ----------
    if (pid < NPRE) {
        if (pid == 0) {
            float a0=0.f, a1=0.f, a2=0.f, a3=0.f;
            #pragma unroll 2
            for (int n = 0; n < 252; n += 4) {
                a0 += __ldg(pos + (n+0)*NH + tid);
                a1 += __ldg(pos + (n+1)*NH + tid);
                a2 += __ldg(pos + (n+2)*NH + tid);
                a3 += __ldg(pos + (n+3)*NH + tid);
            }
            a0 += __ldg(pos + 252*NH + tid);
            a1 += __ldg(pos + 253*NH + tid);
            g_constvec[tid] = (float)NN * b_enc[tid] + ((a0+a1)+(a2+a3));
            __threadfence();
            __syncthreads();
            if (tid == 0) atomicAdd(&g_flag1, 1);
        } else if (pid <= 34) {
            int j = (pid-1)*128 + tid;
            if (j < NN*NL) {                         // M
                g_M[j] = dot128(pos4 + (j>>4)*32, W4 + (j&15)*32);
            } else if (j < NN*NL + NL*NL) {          // G
                int k = j - NN*NL;
                g_G[k] = dot128(W4 + (k>>4)*32, W4 + (k&15)*32);
            }
        } else {
            if (tid == 0) { while (ld_acq(&g_flag1) == 0) {} }
            __syncthreads();
            const float4* cv4 = (const float4*)g_constvec;
            int j = (pid-35)*128 + tid;
            if (j < NN) {                            // D2
                g_D2[j] = dot128(pos4 + j*32, cv4);
            } else if (j < NN + NL) {                // u
                g_u[j-NN] = dot128(W4 + (j-NN)*32, cv4);
            } else if (j < NN + 2*NL) {              // wb
                g_wb[j-NN-NL] = dot128(W4 + (j-NN-NL)*32, (const float4*)b_enc);
            } else if (j == NN + 2*NL) {             // s0
                g_s0pad[0] = dot128((const float4*)b_enc, cv4);
            }
        }
        __threadfence();
        __syncthreads();
        if (tid == 0) atomicAdd(&g_done, 1);
    }

    // ---------- warp-per-pair main path (no __syncthreads below) ----------
    const int pair = pid*4 + wrp;
    const float4* __restrict__ xp4 = (const float4*)(x + (size_t)pair * XPP);
    float4* __restrict__ xc4 = (float4*)(x_copy + (size_t)pair * XPP);

    // Pass 1: stream x (cached) + passthrough copy + xsum partials.
    // lane covers float4 index i = j*32+lane -> row n = j*8 + r, quarter q.
    float ls0=0.f, ls1=0.f, ls2=0.f, ls3=0.f;
    #pragma unroll 8
    for (int j = 0; j < 32; j++) {
        int i = j*32 + lane;
        if (i < XPP/4) {
            float4 f = xp4[i];
            __stcs(xc4 + i, f);
            ls0 += f.x; ls1 += f.y; ls2 += f.z; ls3 += f.w;
        }
    }
    // butterfly over q-classes: every lane ends with xsum[4q..4q+3]
    #pragma unroll
    for (int m = 4; m <= 16; m <<= 1) {
        ls0 += __shfl_xor_sync(0xffffffffu, ls0, m);
        ls1 += __shfl_xor_sync(0xffffffffu, ls1, m);
        ls2 += __shfl_xor_sync(0xffffffffu, ls2, m);
        ls3 += __shfl_xor_sync(0xffffffffu, ls3, m);
    }

    // wait for precompute (first pairs only; nearly-free afterwards)
    while (ld_acq(&g_done) < NPRE) {}

    // materialize xsum[0..15] per lane: xsum[4a+b] lives in lane a's ls_b
    float xs[16];
    #pragma unroll
    for (int a = 0; a < 4; a++) {
        xs[4*a+0] = __shfl_sync(0xffffffffu, ls0, a);
        xs[4*a+1] = __shfl_sync(0xffffffffu, ls1, a);
        xs[4*a+2] = __shfl_sync(0xffffffffu, ls2, a);
        xs[4*a+3] = __shfl_sync(0xffffffffu, ls3, a);
    }
    float4 xsq = make_float4(ls0, ls1, ls2, ls3);   // own quarter of xsum

    // v (own quarter) = u_q + sum_l' xsum[l'] * G[l'][quarter q]
    const float4* __restrict__ G4 = (const float4*)g_G;   // [16][4] float4
    float4 vq = __ldg(&((const float4*)g_u)[q]);
    #pragma unroll
    for (int lp = 0; lp < 16; lp++) {
        float4 g = __ldg(&G4[lp*4 + q]);
        vq.x += xs[lp]*g.x; vq.y += xs[lp]*g.y; vq.z += xs[lp]*g.z; vq.w += xs[lp]*g.w;
    }
    // sS = s0 + xsum . wb   (redundant per lane)
    float sS = __ldg(&g_s0pad[0]);
    {
        const float4* __restrict__ wb4 = (const float4*)g_wb;
        #pragma unroll
        for (int a = 0; a < 4; a++) {
            float4 w = __ldg(&wb4[a]);
            sS += xs[4*a+0]*w.x + xs[4*a+1]*w.y + xs[4*a+2]*w.z + xs[4*a+3]*w.w;
        }
    }

    // Pass 2: fused score + pool (x re-read: L1/L2-hot)
    const float4* __restrict__ M4 = (const float4*)g_M;   // [NN][4] float4
    float p0=0.f, p1=0.f, p2=0.f, p3=0.f, myabs=0.f;
    #pragma unroll 8
    for (int j = 0; j < 32; j++) {
        int i = j*32 + lane;
        int n = j*8 + r;
        float4 f = make_float4(0.f,0.f,0.f,0.f);
        float4 m = make_float4(0.f,0.f,0.f,0.f);
        float d2 = 0.f;
        if (n < NN) {
            f  = xp4[i];
            m  = __ldg(&M4[n*4 + q]);
            d2 = __ldg(g_D2 + n);
        }
        float part = f.x*vq.x + f.y*vq.y + f.z*vq.z + f.w*vq.w
                   + xsq.x*m.x + xsq.y*m.y + xsq.z*m.z + xsq.w*m.w;
        part += __shfl_xor_sync(0xffffffffu, part, 1);
        part += __shfl_xor_sync(0xffffffffu, part, 2);
        float a = part + sS + d2;                 // score[n] (zeros beyond NN)
        if (n < NN) {
            p0 += f.x*a; p1 += f.y*a; p2 += f.z*a; p3 += f.w*a;
            if (q == 0) myabs += fabsf(a);
        }
    }
    // reduce pooled quarters + |score| total
    #pragma unroll
    for (int m = 4; m <= 16; m <<= 1) {
        p0 += __shfl_xor_sync(0xffffffffu, p0, m);
        p1 += __shfl_xor_sync(0xffffffffu, p1, m);
        p2 += __shfl_xor_sync(0xffffffffu, p2, m);
        p3 += __shfl_xor_sync(0xffffffffu, p3, m);
        myabs += __shfl_xor_sync(0xffffffffu, myabs, m);
    }
    float inv = 1.0f / __shfl_sync(0xffffffffu, myabs, 0);

    // materialize pooled[0..15] (unnormalized)
    float po[16];
    #pragma unroll
    for (int a = 0; a < 4; a++) {
        po[4*a+0] = __shfl_sync(0xffffffffu, p0, a);
        po[4*a+1] = __shfl_sync(0xffffffffu, p1, a);
        po[4*a+2] = __shfl_sync(0xffffffffu, p2, a);
        po[4*a+3] = __shfl_sync(0xffffffffu, p3, a);
    }

    // FF hidden: lane owns h = lane + 32k, k=0..3
    float hdn[4];
    #pragma unroll
    for (int k = 0; k < 4; k++) {
        int h = lane + 32*k;
        float a = 0.f;
        #pragma unroll
        for (int l = 0; l < NL; l++) a += po[l] * __ldg(W1 + l*NH + h);
        a = __ldg(b1 + h) + a * inv;
        hdn[k] = a > 0.f ? a : 0.2f * a;
    }

    // W2: lanes 0..23 accumulate float4 of p; hdn broadcast via static-index shfl
    const float4* __restrict__ W24 = (const float4*)W2;   // [h][24] float4
    float4 acc = make_float4(0.f, 0.f, 0.f, 0.f);
    #pragma unroll
    for (int k = 0; k < 4; k++) {
        #pragma unroll 8
        for (int hh = 0; hh < 32; hh++) {
            float hv = __shfl_sync(0xffffffffu, hdn[k], hh);
            if (lane < 24) {
                float4 w4 = __ldg(&W24[(k*32 + hh)*24 + lane]);
                acc.x += hv*w4.x; acc.y += hv*w4.y; acc.z += hv*w4.z; acc.w += hv*w4.w;
            }
        }
    }
    if (lane < 24) {
        int b = pair >> 6, d = pair & 63;
        float* dst = out_t + b*(NP*ND) + d;
        float4 bb = __ldg(&((const float4*)b2)[lane]);
        int p = lane*4;
        dst[(p+0)*ND] = acc.x + bb.x;
        dst[(p+1)*ND] = acc.y + bb.y;
        dst[(p+2)*ND] = acc.z + bb.z;
        dst[(p+3)*ND] = acc.w + bb.w;
    }
}

extern "C" void kernel_launch(void* const* d_in, const int* in_sizes, int n_in,
                              void* d_out, int out_size) {
    const float* x     = (const float*)d_in[0];
    const float* W_enc = (const float*)d_in[1];
    const float* b_enc = (const float*)d_in[2];
    const float* W1    = (const float*)d_in[3];
    const float* b1    = (const float*)d_in[4];
    const float* W2    = (const float*)d_in[5];
    const float* b2    = (const float*)d_in[6];
    const float* pos   = (const float*)d_in[7];

    float* out   = (float*)d_out;          // (B,P,D) first
    float* xcopy = out + OUT_T_ELEMS;      // then p = x passthrough

    k_all<<<PAIRS/4, 128>>>(x, xcopy, W_enc, b_enc, pos, W1, b1, W2, b2, out);
}